// round 3
// baseline (speedup 1.0000x reference)
#include <cuda_runtime.h>

// TokenMapper: out[b,p,:] = (relu(emb[hash[b,p] + p*257] @ W1 + b1) @ W2 + b2) + pe[p]
//
// Algorithmic reduction: only 16*257 = 4112 distinct embedding rows exist, so the
// whole MLP is precomputed into a table T[4112,1024] (bias + pe folded in), and the
// per-(b,p) output is a pure row gather. FLOPs drop 16x vs the naive formulation.

#define P_PARTS 16
#define NK1     257                 // table rows per part (NUM_K + 1)
#define ROWS    (P_PARTS * NK1)     // 4112
#define VAE     768
#define OUTD    1024
#define BATCH   4096

// Scratch (alloc-free rule: __device__ globals). Referenced by symbol inside
// kernels — kernel_launch calls NO runtime API except kernel launches.
__device__ float g_H[ROWS * OUTD];  // relu(emb@W1+b1)
__device__ float g_T[ROWS * OUTD];  // g_H@W2 + b2 + pe[part]  (final gather table)

// ---------------------------------------------------------------------------
// 128x128 register-tiled SGEMM, 256 threads, 8x8 per-thread microtile, with
// software-pipelined global->reg prefetch of the next K-slice.
// C[M,N] = A[M,K] @ B[K,N] + bias[N]  (+ optional relu, + optional pe[row/257])
// N fixed at 1024; K divides BK exactly (768 / 1024). Only M guarded (4112).
//   STAGE==1: A = emb (param),  C = g_H, RELU,  no pe
//   STAGE==2: A = g_H (symbol), C = g_T, no relu, +pe
// ---------------------------------------------------------------------------
template<int STAGE>
__global__ __launch_bounds__(256)
void sgemm_bias_kernel(const float* __restrict__ Aparam,
                       const float* __restrict__ Bw,
                       const float* __restrict__ bias,
                       const float* __restrict__ pe,
                       int M, int K)
{
    constexpr int BM = 128, BN = 128, BK = 8, TM = 8, TN = 8;
    constexpr int N = OUTD;
    constexpr bool RELU   = (STAGE == 1);
    constexpr bool ADD_PE = (STAGE == 2);

    const float* A = (STAGE == 1) ? Aparam : (const float*)g_H;
    float*       C = (STAGE == 1) ? g_H : g_T;

    __shared__ float As[BK][BM + 4];   // transposed A tile (+pad)
    __shared__ float Bs[BK][BN];

    const int tid   = threadIdx.x;
    const int cCol  = blockIdx.x * BN;   // N-tile origin
    const int cRowB = blockIdx.y * BM;   // M-tile origin

    // A tile load: 128x8 floats, one float4 per thread
    const int aRow = tid >> 1;           // 0..127
    const int aCol = (tid & 1) * 4;      // 0 or 4
    // B tile load: 8x128 floats, one float4 per thread
    const int bRow = tid >> 5;           // 0..7
    const int bCol = (tid & 31) * 4;     // 0..124

    // compute microtile origin
    const int tRow = (tid >> 4) * TM;    // 0..120
    const int tCol = (tid & 15) * TN;    // 0..120

    float acc[TM][TN];
    #pragma unroll
    for (int i = 0; i < TM; i++)
        #pragma unroll
        for (int j = 0; j < TN; j++)
            acc[i][j] = 0.0f;

    const int  gARow  = cRowB + aRow;
    const bool aValid = (gARow < M);
    const float* Ap = A  + (size_t)(aValid ? gARow : 0) * K + aCol;
    const float* Bp = Bw + (size_t)bRow * N + cCol + bCol;

    // --- prologue: fetch slice 0 into registers ---
    float4 av = make_float4(0.f, 0.f, 0.f, 0.f);
    if (aValid) av = *(const float4*)(Ap);
    float4 bv = *(const float4*)(Bp);

    for (int k0 = 0; k0 < K; k0 += BK) {
        // store the in-flight slice into smem
        As[aCol + 0][aRow] = av.x;
        As[aCol + 1][aRow] = av.y;
        As[aCol + 2][aRow] = av.z;
        As[aCol + 3][aRow] = av.w;
        *(float4*)&Bs[bRow][bCol] = bv;
        __syncthreads();

        // prefetch next slice into registers (overlaps with FMA block below)
        const int kn = k0 + BK;
        if (kn < K) {
            av = aValid ? *(const float4*)(Ap + kn) : make_float4(0.f,0.f,0.f,0.f);
            bv = *(const float4*)(Bp + (size_t)kn * N);
        }

        #pragma unroll
        for (int k = 0; k < BK; k++) {
            float ar[TM], br[TN];
            #pragma unroll
            for (int i = 0; i < TM; i++) ar[i] = As[k][tRow + i];
            *(float4*)&br[0] = *(const float4*)&Bs[k][tCol];
            *(float4*)&br[4] = *(const float4*)&Bs[k][tCol + 4];
            #pragma unroll
            for (int i = 0; i < TM; i++)
                #pragma unroll
                for (int j = 0; j < TN; j++)
                    acc[i][j] = fmaf(ar[i], br[j], acc[i][j]);
        }
        __syncthreads();
    }

    // Epilogue: bias (+relu) (+pe), vectorized stores
    #pragma unroll
    for (int i = 0; i < TM; i++) {
        const int row = cRowB + tRow + i;
        if (row < M) {
            const int part = row / NK1;                 // only used when ADD_PE
            float* Crow = C + (size_t)row * N;
            #pragma unroll
            for (int j = 0; j < TN; j += 4) {
                const int col = cCol + tCol + j;
                float4 bsv = *(const float4*)&bias[col];
                float4 v;
                v.x = acc[i][j + 0] + bsv.x;
                v.y = acc[i][j + 1] + bsv.y;
                v.z = acc[i][j + 2] + bsv.z;
                v.w = acc[i][j + 3] + bsv.w;
                if (RELU) {
                    v.x = fmaxf(v.x, 0.f); v.y = fmaxf(v.y, 0.f);
                    v.z = fmaxf(v.z, 0.f); v.w = fmaxf(v.w, 0.f);
                }
                if (ADD_PE) {
                    float4 pv = *(const float4*)&pe[(size_t)part * N + col];
                    v.x += pv.x; v.y += pv.y; v.z += pv.z; v.w += pv.w;
                }
                *(float4*)&Crow[col] = v;
            }
        }
    }
}

// ---------------------------------------------------------------------------
// Gather: out[i,:] = g_T[(i%16)*257 + hashes[i], :], one block per output row.
// 256 threads x float4 = 1024 floats per row.
// ---------------------------------------------------------------------------
__global__ __launch_bounds__(256)
void gather_kernel(const int* __restrict__ hashes, float* __restrict__ out)
{
    const int i = blockIdx.x;                 // 0..65535  (= b*16 + p)
    const int p = i & (P_PARTS - 1);
    const int h = __ldg(&hashes[i]);
    const float4* src = (const float4*)(g_T + (size_t)(p * NK1 + h) * OUTD);
    float4*       dst = (float4*)(out + (size_t)i * OUTD);
    dst[threadIdx.x] = src[threadIdx.x];
}

// ---------------------------------------------------------------------------
extern "C" void kernel_launch(void* const* d_in, const int* in_sizes, int n_in,
                              void* d_out, int out_size)
{
    const int*   hashes = (const int*)  d_in[0];
    const float* emb    = (const float*)d_in[1];
    const float* W1     = (const float*)d_in[2];
    const float* b1     = (const float*)d_in[3];
    const float* W2     = (const float*)d_in[4];
    const float* b2     = (const float*)d_in[5];
    const float* pe     = (const float*)d_in[6];
    float*       out    = (float*)d_out;

    dim3 grid(OUTD / 128, (ROWS + 127) / 128);   // 8 x 33

    // Stage 1: g_H = relu(emb @ W1 + b1)          [4112, 1024], K = 768
    sgemm_bias_kernel<1><<<grid, 256>>>(emb, W1, b1, nullptr, ROWS, VAE);
    // Stage 2: g_T = g_H @ W2 + b2 + pe[part]     [4112, 1024], K = 1024
    sgemm_bias_kernel<2><<<grid, 256>>>(nullptr, W2, b2, pe, ROWS, OUTD);
    // Stage 3: gather rows into the 256 MB output
    gather_kernel<<<BATCH * P_PARTS, 256>>>(hashes, out);
}

// round 6
// speedup vs baseline: 1.4435x; 1.4435x over previous
#include <cuda_runtime.h>
#include <cuda_bf16.h>
#include <cstdint>

// TokenMapper: out[b,p,:] = (relu(emb[hash[b,p]+p*257] @ W1 + b1) @ W2 + b2) + pe[p]
// Only 16*257=4112 distinct rows -> precompute table T[4112,1024], then gather.
// GEMMs on warp-level mma.sync bf16 (sm_100-target-safe; tcgen05 needs sm_100a
// which this toolchain's compute_100 virtual arch rejects), with bf16 hi/lo
// split (3 MMAs) for fp32-grade accuracy.

#define P_PARTS 16
#define NK1     257
#define ROWS    (P_PARTS * NK1)     // 4112
#define VAE     768
#define OUTD    1024
#define BATCH   4096

// ---------------- scratch (__device__ globals; alloc-free rule) ----------------
__device__ __align__(16) __nv_bfloat16 g_Ah[ROWS * VAE];    // emb hi
__device__ __align__(16) __nv_bfloat16 g_Al[ROWS * VAE];    // emb lo
__device__ __align__(16) __nv_bfloat16 g_B1h[OUTD * VAE];   // W1^T hi  [n][k]
__device__ __align__(16) __nv_bfloat16 g_B1l[OUTD * VAE];
__device__ __align__(16) __nv_bfloat16 g_B2h[OUTD * OUTD];  // W2^T hi  [n][k]
__device__ __align__(16) __nv_bfloat16 g_B2l[OUTD * OUTD];
__device__ __align__(16) __nv_bfloat16 g_Hh[ROWS * OUTD];   // relu(emb@W1+b1) hi
__device__ __align__(16) __nv_bfloat16 g_Hl[ROWS * OUTD];
__device__ __align__(16) float         g_T [ROWS * OUTD];   // final gather table

// ---------------- PTX helpers (all valid at sm_80+, compile on sm_100) --------
__device__ __forceinline__ uint32_t smem_u32(const void* p) {
    uint32_t a;
    asm("{ .reg .u64 t; cvta.to.shared.u64 t, %1; cvt.u32.u64 %0, t; }" : "=r"(a) : "l"(p));
    return a;
}
__device__ __forceinline__ void cp16(uint32_t dst, const void* src) {
    asm volatile("cp.async.cg.shared.global [%0], [%1], 16;" :: "r"(dst), "l"(src));
}
#define CP_COMMIT() asm volatile("cp.async.commit_group;" ::: "memory")
#define CP_WAIT(n)  asm volatile("cp.async.wait_group %0;" :: "n"(n) : "memory")

__device__ __forceinline__ void ldm_x4(uint32_t* r, uint32_t addr) {
    asm volatile("ldmatrix.sync.aligned.m8n8.x4.shared.b16 {%0,%1,%2,%3}, [%4];"
        : "=r"(r[0]), "=r"(r[1]), "=r"(r[2]), "=r"(r[3]) : "r"(addr));
}
__device__ __forceinline__ void mma_bf16(float* c, const uint32_t* a,
                                         uint32_t b0, uint32_t b1) {
    asm volatile("mma.sync.aligned.m16n8k16.row.col.f32.bf16.bf16.f32 "
        "{%0,%1,%2,%3}, {%4,%5,%6,%7}, {%8,%9}, {%0,%1,%2,%3};"
        : "+f"(c[0]), "+f"(c[1]), "+f"(c[2]), "+f"(c[3])
        : "r"(a[0]), "r"(a[1]), "r"(a[2]), "r"(a[3]), "r"(b0), "r"(b1));
}

// ---------------- prep kernels: bf16 hi/lo splits ----------------
__global__ void split_emb_kernel(const float* __restrict__ src)
{
    const int n = ROWS * VAE;
    for (int i = blockIdx.x * blockDim.x + threadIdx.x; i < n; i += gridDim.x * blockDim.x) {
        float v = src[i];
        __nv_bfloat16 h = __float2bfloat16(v);
        g_Ah[i] = h;
        g_Al[i] = __float2bfloat16(v - __bfloat162float(h));
    }
}

// src [Kdim][1024] -> g_B?h/l [1024][Kdim] (transposed, split)
template<int WHICH>
__global__ void transpose_split_kernel(const float* __restrict__ src, int Kdim)
{
    __nv_bfloat16* dh = (WHICH == 1) ? g_B1h : g_B2h;
    __nv_bfloat16* dl = (WHICH == 1) ? g_B1l : g_B2l;
    __shared__ float t[32][33];
    const int n0 = blockIdx.x * 32, k0 = blockIdx.y * 32;
    const int x = threadIdx.x, y = threadIdx.y;           // block (32, 8)
    #pragma unroll
    for (int i = 0; i < 32; i += 8)
        t[y + i][x] = src[(size_t)(k0 + y + i) * OUTD + n0 + x];
    __syncthreads();
    #pragma unroll
    for (int i = 0; i < 32; i += 8) {
        const int n = n0 + y + i, k = k0 + x;
        float v = t[x][y + i];
        __nv_bfloat16 h = __float2bfloat16(v);
        dh[(size_t)n * Kdim + k] = h;
        dl[(size_t)n * Kdim + k] = __float2bfloat16(v - __bfloat162float(h));
    }
}

// ---------------- mma.sync GEMM: C[128x64 tile] = A @ B^T (split, 3-mma) ------
// STAGE 1: A=(g_Ah,g_Al)[ROWS,768],  B=(g_B1h,l)[1024,768]  -> relu+b1 -> g_Hh/g_Hl
// STAGE 2: A=(g_Hh,g_Hl)[ROWS,1024], B=(g_B2h,l)[1024,1024] -> +b2+pe  -> g_T
template<int STAGE>
__global__ __launch_bounds__(256)
void mlp_mma_kernel(const float* __restrict__ bias, const float* __restrict__ pe)
{
    constexpr int K  = (STAGE == 1) ? VAE : OUTD;
    constexpr int KT = K / 16;
    constexpr int AP = 48;                      // smem row pitch (32B data + 16B pad)
    constexpr int A_BYTES = 128 * AP;           // 6144 per array
    constexpr int B_BYTES = 64 * AP;            // 3072 per array
    constexpr int STG = 2 * A_BYTES + 2 * B_BYTES;  // 18432 per stage

    const __nv_bfloat16* Ah = (STAGE == 1) ? g_Ah  : g_Hh;
    const __nv_bfloat16* Al = (STAGE == 1) ? g_Al  : g_Hl;
    const __nv_bfloat16* Bh = (STAGE == 1) ? g_B1h : g_B2h;
    const __nv_bfloat16* Bl = (STAGE == 1) ? g_B1l : g_B2l;

    __shared__ __align__(16) char smem[2 * STG];    // 36864 bytes (static)
    float* epi = (float*)smem;                      // epilogue alias: 128*68*4=34816

    const uint32_t sb  = smem_u32(smem);
    const int tid   = threadIdx.x;
    const int nBase = blockIdx.x * 64;
    const int mBase = blockIdx.y * 128;
    const int w = tid >> 5, lane = tid & 31;
    const int wm = (w >> 1) * 32;               // warp m-origin (4 warps down)
    const int wn = (w & 1) * 32;                // warp n-origin (2 warps across)

    float acc[2][4][4];
    #pragma unroll
    for (int a = 0; a < 2; a++)
        #pragma unroll
        for (int b = 0; b < 4; b++)
            #pragma unroll
            for (int c = 0; c < 4; c++) acc[a][b][c] = 0.f;

    // --- cp.async stage loader: 768 x 16B per stage (A hi/lo 512, B hi/lo 256)
    auto load_stage = [&](int kt, int s) {
        const uint32_t base = sb + s * STG;
        #pragma unroll
        for (int i = tid; i < 768; i += 256) {
            if (i < 512) {
                const int arr = i >> 8, rem = i & 255, row = rem >> 1, c = rem & 1;
                int rg = mBase + row; if (rg >= ROWS) rg = ROWS - 1;
                const __nv_bfloat16* src = (arr ? Al : Ah) + (size_t)rg * K + kt * 16 + c * 8;
                cp16(base + arr * A_BYTES + row * AP + c * 16, src);
            } else {
                const int j = i - 512, arr = j >> 7, rem = j & 127, row = rem >> 1, c = rem & 1;
                const __nv_bfloat16* src = (arr ? Bl : Bh) + (size_t)(nBase + row) * K + kt * 16 + c * 8;
                cp16(base + 2 * A_BYTES + arr * B_BYTES + row * AP + c * 16, src);
            }
        }
    };

    load_stage(0, 0); CP_COMMIT();

    // ldmatrix x4 lane addressing: mats = [rows 0-7|8-15] x [k-chunk 0|1]
    const int lrow   = (lane & 7) + ((lane >> 3) & 1) * 8;
    const int lchunk = (lane >> 4) * 16;

    for (int kt = 0; kt < KT; kt++) {
        const int s = kt & 1;
        if (kt + 1 < KT) { load_stage(kt + 1, s ^ 1); CP_COMMIT(); CP_WAIT(1); }
        else             { CP_WAIT(0); }
        __syncthreads();

        const uint32_t base = sb + s * STG;
        uint32_t ah[2][4], al[2][4], bh[2][4], bl[2][4];
        #pragma unroll
        for (int mf = 0; mf < 2; mf++) {
            const uint32_t a = base + (wm + mf * 16 + lrow) * AP + lchunk;
            ldm_x4(ah[mf], a);
            ldm_x4(al[mf], a + A_BYTES);
        }
        #pragma unroll
        for (int nt = 0; nt < 2; nt++) {
            const uint32_t b = base + 2 * A_BYTES + (wn + nt * 16 + lrow) * AP + lchunk;
            ldm_x4(bh[nt], b);
            ldm_x4(bl[nt], b + B_BYTES);
        }
        #pragma unroll
        for (int mf = 0; mf < 2; mf++)
            #pragma unroll
            for (int nt = 0; nt < 2; nt++) {
                // B frag n0-7 = {r0,r2}, n8-15 = {r1,r3}
                mma_bf16(acc[mf][nt * 2],     ah[mf], bh[nt][0], bh[nt][2]);  // hi*hi
                mma_bf16(acc[mf][nt * 2 + 1], ah[mf], bh[nt][1], bh[nt][3]);
                mma_bf16(acc[mf][nt * 2],     ah[mf], bl[nt][0], bl[nt][2]);  // hi*lo
                mma_bf16(acc[mf][nt * 2 + 1], ah[mf], bl[nt][1], bl[nt][3]);
                mma_bf16(acc[mf][nt * 2],     al[mf], bh[nt][0], bh[nt][2]);  // lo*hi
                mma_bf16(acc[mf][nt * 2 + 1], al[mf], bh[nt][1], bh[nt][3]);
            }
        __syncthreads();
    }

    // --- epilogue phase 1: accum regs -> smem staging [128][68] (aliases stages)
    #pragma unroll
    for (int mf = 0; mf < 2; mf++) {
        const int r0 = wm + mf * 16 + (lane >> 2);
        #pragma unroll
        for (int nf = 0; nf < 4; nf++) {
            const int c0 = wn + nf * 8 + (lane & 3) * 2;
            epi[r0 * 68 + c0]           = acc[mf][nf][0];
            epi[r0 * 68 + c0 + 1]       = acc[mf][nf][1];
            epi[(r0 + 8) * 68 + c0]     = acc[mf][nf][2];
            epi[(r0 + 8) * 68 + c0 + 1] = acc[mf][nf][3];
        }
    }
    __syncthreads();

    // --- epilogue phase 2: smem -> global with bias/relu/pe, vectorized
    if constexpr (STAGE == 1) {
        for (int i = tid; i < 1024; i += 256) {     // 128 rows x 8 chunks of 8 cols
            const int r = i >> 3, c8 = (i & 7) * 8;
            const int grow = mBase + r;
            if (grow < ROWS) {
                __nv_bfloat16 hh[8], ll[8];
                #pragma unroll
                for (int j = 0; j < 8; j++) {
                    float v = epi[r * 68 + c8 + j] + __ldg(&bias[nBase + c8 + j]);
                    v = fmaxf(v, 0.f);
                    __nv_bfloat16 h = __float2bfloat16(v);
                    hh[j] = h;
                    ll[j] = __float2bfloat16(v - __bfloat162float(h));
                }
                const size_t o = (size_t)grow * OUTD + nBase + c8;
                *(uint4*)&g_Hh[o] = *(const uint4*)hh;
                *(uint4*)&g_Hl[o] = *(const uint4*)ll;
            }
        }
    } else {
        for (int i = tid; i < 2048; i += 256) {     // 128 rows x 16 chunks of 4 cols
            const int r = i >> 4, c4 = (i & 15) * 4;
            const int grow = mBase + r;
            if (grow < ROWS) {
                const int part = grow / NK1;
                float o[4];
                #pragma unroll
                for (int j = 0; j < 4; j++) {
                    const int col = nBase + c4 + j;
                    o[j] = epi[r * 68 + c4 + j] + __ldg(&bias[col])
                         + __ldg(&pe[(size_t)part * OUTD + col]);
                }
                *(uint4*)&g_T[(size_t)grow * OUTD + nBase + c4] = *(const uint4*)o;
            }
        }
    }
}

// ---------------- gather: out[i,:] = g_T[(i&15)*257 + hash[i], :] ----------------
__global__ __launch_bounds__(256)
void gather_kernel(const int* __restrict__ hashes, float* __restrict__ out)
{
    const int i = blockIdx.x;                          // b*16 + p
    const int p = i & (P_PARTS - 1);
    const int h = __ldg(&hashes[i]);
    const float4* src = (const float4*)(g_T + (size_t)(p * NK1 + h) * OUTD);
    float4*       dst = (float4*)(out + (size_t)i * OUTD);
    dst[threadIdx.x] = src[threadIdx.x];
}

// ---------------------------------------------------------------------------
extern "C" void kernel_launch(void* const* d_in, const int* in_sizes, int n_in,
                              void* d_out, int out_size)
{
    const int*   hashes = (const int*)  d_in[0];
    const float* emb    = (const float*)d_in[1];
    const float* W1     = (const float*)d_in[2];
    const float* b1     = (const float*)d_in[3];
    const float* W2     = (const float*)d_in[4];
    const float* b2     = (const float*)d_in[5];
    const float* pe     = (const float*)d_in[6];
    float*       out    = (float*)d_out;

    split_emb_kernel<<<512, 256>>>(emb);
    transpose_split_kernel<1><<<dim3(32, 24), dim3(32, 8)>>>(W1, VAE);   // W1 [768][1024]
    transpose_split_kernel<2><<<dim3(32, 32), dim3(32, 8)>>>(W2, OUTD);  // W2 [1024][1024]

    dim3 grid(OUTD / 64, (ROWS + 127) / 128);                            // 16 x 33
    mlp_mma_kernel<1><<<grid, 256>>>(b1, nullptr);
    mlp_mma_kernel<2><<<grid, 256>>>(b2, pe);

    gather_kernel<<<BATCH * P_PARTS, 256>>>(hashes, out);
}

// round 8
// speedup vs baseline: 1.5134x; 1.0485x over previous
#include <cuda_runtime.h>
#include <cuda_bf16.h>
#include <cstdint>

// TokenMapper: out[b,p,:] = (relu(emb[hash[b,p]+p*257] @ W1 + b1) @ W2 + b2) + pe[p]
// Only 16*257=4112 distinct rows -> precompute table T[4112,1024], then gather.
// GEMMs on warp-level mma.sync bf16 (tcgen05 unavailable: toolchain targets
// compute_100, not 100a) with bf16 hi/lo split (3 MMAs) for fp32-grade accuracy.
// R8: CTA tile 128x128, warp tile 32x64, product-grouped MMA order, direct
// epilogue, streaming stores in gather.

#define P_PARTS 16
#define NK1     257
#define ROWS    (P_PARTS * NK1)     // 4112
#define VAE     768
#define OUTD    1024
#define BATCH   4096

// ---------------- scratch (__device__ globals; alloc-free rule) ----------------
__device__ __align__(16) __nv_bfloat16 g_Ah[ROWS * VAE];    // emb hi
__device__ __align__(16) __nv_bfloat16 g_Al[ROWS * VAE];    // emb lo
__device__ __align__(16) __nv_bfloat16 g_B1h[OUTD * VAE];   // W1^T hi  [n][k]
__device__ __align__(16) __nv_bfloat16 g_B1l[OUTD * VAE];
__device__ __align__(16) __nv_bfloat16 g_B2h[OUTD * OUTD];  // W2^T hi  [n][k]
__device__ __align__(16) __nv_bfloat16 g_B2l[OUTD * OUTD];
__device__ __align__(16) __nv_bfloat16 g_Hh[ROWS * OUTD];   // relu(emb@W1+b1) hi
__device__ __align__(16) __nv_bfloat16 g_Hl[ROWS * OUTD];
__device__ __align__(16) float         g_T [ROWS * OUTD];   // final gather table

// ---------------- PTX helpers (valid at sm_80+, compile on sm_100) ------------
__device__ __forceinline__ uint32_t smem_u32(const void* p) {
    uint32_t a;
    asm("{ .reg .u64 t; cvta.to.shared.u64 t, %1; cvt.u32.u64 %0, t; }" : "=r"(a) : "l"(p));
    return a;
}
__device__ __forceinline__ void cp16(uint32_t dst, const void* src) {
    asm volatile("cp.async.cg.shared.global [%0], [%1], 16;" :: "r"(dst), "l"(src));
}
#define CP_COMMIT() asm volatile("cp.async.commit_group;" ::: "memory")
#define CP_WAIT(n)  asm volatile("cp.async.wait_group %0;" :: "n"(n) : "memory")

__device__ __forceinline__ void ldm_x4(uint32_t* r, uint32_t addr) {
    asm volatile("ldmatrix.sync.aligned.m8n8.x4.shared.b16 {%0,%1,%2,%3}, [%4];"
        : "=r"(r[0]), "=r"(r[1]), "=r"(r[2]), "=r"(r[3]) : "r"(addr));
}
__device__ __forceinline__ void mma_bf16(float* c, const uint32_t* a,
                                         uint32_t b0, uint32_t b1) {
    asm volatile("mma.sync.aligned.m16n8k16.row.col.f32.bf16.bf16.f32 "
        "{%0,%1,%2,%3}, {%4,%5,%6,%7}, {%8,%9}, {%0,%1,%2,%3};"
        : "+f"(c[0]), "+f"(c[1]), "+f"(c[2]), "+f"(c[3])
        : "r"(a[0]), "r"(a[1]), "r"(a[2]), "r"(a[3]), "r"(b0), "r"(b1));
}

// ---------------- prep kernels: bf16 hi/lo splits ----------------
__global__ void split_emb_kernel(const float* __restrict__ src)
{
    const int n = ROWS * VAE;
    for (int i = blockIdx.x * blockDim.x + threadIdx.x; i < n; i += gridDim.x * blockDim.x) {
        float v = src[i];
        __nv_bfloat16 h = __float2bfloat16(v);
        g_Ah[i] = h;
        g_Al[i] = __float2bfloat16(v - __bfloat162float(h));
    }
}

// src [Kdim][1024] -> g_B?h/l [1024][Kdim] (transposed, split)
template<int WHICH>
__global__ void transpose_split_kernel(const float* __restrict__ src, int Kdim)
{
    __nv_bfloat16* dh = (WHICH == 1) ? g_B1h : g_B2h;
    __nv_bfloat16* dl = (WHICH == 1) ? g_B1l : g_B2l;
    __shared__ float t[32][33];
    const int n0 = blockIdx.x * 32, k0 = blockIdx.y * 32;
    const int x = threadIdx.x, y = threadIdx.y;           // block (32, 8)
    #pragma unroll
    for (int i = 0; i < 32; i += 8)
        t[y + i][x] = src[(size_t)(k0 + y + i) * OUTD + n0 + x];
    __syncthreads();
    #pragma unroll
    for (int i = 0; i < 32; i += 8) {
        const int n = n0 + y + i, k = k0 + x;
        float v = t[x][y + i];
        __nv_bfloat16 h = __float2bfloat16(v);
        dh[(size_t)n * Kdim + k] = h;
        dl[(size_t)n * Kdim + k] = __float2bfloat16(v - __bfloat162float(h));
    }
}

// ---------------- mma.sync GEMM: C[128x128 tile] = A @ B^T (split, 3-mma) -----
// STAGE 1: A=(g_Ah,g_Al)[ROWS,768],  B=(g_B1h,l)[1024,768]  -> relu+b1 -> g_Hh/g_Hl
// STAGE 2: A=(g_Hh,g_Hl)[ROWS,1024], B=(g_B2h,l)[1024,1024] -> +b2+pe  -> g_T
template<int STAGE>
__global__ __launch_bounds__(256)
void mlp_mma_kernel(const float* __restrict__ bias, const float* __restrict__ pe)
{
    constexpr int K  = (STAGE == 1) ? VAE : OUTD;
    constexpr int KT = K / 16;
    constexpr int AP = 48;                      // smem row pitch (32B data + 16B pad)
    constexpr int ARR_BYTES = 128 * AP;         // 6144 per array (A and B both 128 rows)
    constexpr int STG = 4 * ARR_BYTES;          // Ah,Al,Bh,Bl = 24576 per stage

    const __nv_bfloat16* Ah = (STAGE == 1) ? g_Ah  : g_Hh;
    const __nv_bfloat16* Al = (STAGE == 1) ? g_Al  : g_Hl;
    const __nv_bfloat16* Bh = (STAGE == 1) ? g_B1h : g_B2h;
    const __nv_bfloat16* Bl = (STAGE == 1) ? g_B1l : g_B2l;

    __shared__ __align__(16) char smem[2 * STG];    // 49152 = 48KB exactly

    const uint32_t sb  = smem_u32(smem);
    const int tid   = threadIdx.x;
    const int nBase = blockIdx.x * 128;
    const int mBase = blockIdx.y * 128;
    const int w = tid >> 5, lane = tid & 31;
    const int wm = (w >> 1) * 32;               // 4 warps down (M)
    const int wn = (w & 1) * 64;                // 2 warps across (N)

    float acc[2][8][4];                         // [mf][nf: nt*2+half][4]
    #pragma unroll
    for (int a = 0; a < 2; a++)
        #pragma unroll
        for (int b = 0; b < 8; b++)
            #pragma unroll
            for (int c = 0; c < 4; c++) acc[a][b][c] = 0.f;

    // --- cp.async stage loader: 1024 x 16B per stage (A hi/lo 512, B hi/lo 512)
    auto load_stage = [&](int kt, int s) {
        const uint32_t base = sb + s * STG;
        #pragma unroll
        for (int i = tid; i < 1024; i += 256) {
            const int half = i >> 9;            // 0 = A, 1 = B
            const int j    = i & 511;
            const int arr  = j >> 8, rem = j & 255, row = rem >> 1, c = rem & 1;
            const __nv_bfloat16* src;
            if (half == 0) {
                int rg = mBase + row; if (rg >= ROWS) rg = ROWS - 1;
                src = (arr ? Al : Ah) + (size_t)rg * K + kt * 16 + c * 8;
            } else {
                src = (arr ? Bl : Bh) + (size_t)(nBase + row) * K + kt * 16 + c * 8;
            }
            cp16(base + (half * 2 + arr) * ARR_BYTES + row * AP + c * 16, src);
        }
    };

    load_stage(0, 0); CP_COMMIT();

    // ldmatrix x4 lane addressing: mats = [rows 0-7|8-15] x [k-chunk 0|1]
    const int lrow   = (lane & 7) + ((lane >> 3) & 1) * 8;
    const int lchunk = (lane >> 4) * 16;

    for (int kt = 0; kt < KT; kt++) {
        const int s = kt & 1;
        if (kt + 1 < KT) { load_stage(kt + 1, s ^ 1); CP_COMMIT(); CP_WAIT(1); }
        else             { CP_WAIT(0); }
        __syncthreads();

        const uint32_t base = sb + s * STG;
        uint32_t ah[2][4], al[2][4], bh[4][4], bl[4][4];
        #pragma unroll
        for (int mf = 0; mf < 2; mf++) {
            const uint32_t a = base + (wm + mf * 16 + lrow) * AP + lchunk;
            ldm_x4(ah[mf], a);
            ldm_x4(al[mf], a + ARR_BYTES);
        }
        #pragma unroll
        for (int nt = 0; nt < 4; nt++) {
            const uint32_t b = base + 2 * ARR_BYTES + (wn + nt * 16 + lrow) * AP + lchunk;
            ldm_x4(bh[nt], b);
            ldm_x4(bl[nt], b + ARR_BYTES);
        }
        // Product-grouped ordering: 16 independent MMAs between reuses of any
        // accumulator quad (vs depth-3 back-to-back chains).
        #pragma unroll
        for (int mf = 0; mf < 2; mf++)                      // hi * hi
            #pragma unroll
            for (int nt = 0; nt < 4; nt++) {
                mma_bf16(acc[mf][nt * 2],     ah[mf], bh[nt][0], bh[nt][2]);
                mma_bf16(acc[mf][nt * 2 + 1], ah[mf], bh[nt][1], bh[nt][3]);
            }
        #pragma unroll
        for (int mf = 0; mf < 2; mf++)                      // hi * lo
            #pragma unroll
            for (int nt = 0; nt < 4; nt++) {
                mma_bf16(acc[mf][nt * 2],     ah[mf], bl[nt][0], bl[nt][2]);
                mma_bf16(acc[mf][nt * 2 + 1], ah[mf], bl[nt][1], bl[nt][3]);
            }
        #pragma unroll
        for (int mf = 0; mf < 2; mf++)                      // lo * hi
            #pragma unroll
            for (int nt = 0; nt < 4; nt++) {
                mma_bf16(acc[mf][nt * 2],     al[mf], bh[nt][0], bh[nt][2]);
                mma_bf16(acc[mf][nt * 2 + 1], al[mf], bh[nt][1], bh[nt][3]);
            }
        __syncthreads();
    }

    // --- epilogue: direct stores from accumulators (no smem staging) ---------
    const int r_lane = lane >> 2;               // 0..7
    const int c_lane = (lane & 3) * 2;          // 0,2,4,6
    #pragma unroll
    for (int mf = 0; mf < 2; mf++) {
        #pragma unroll
        for (int half = 0; half < 2; half++) {
            const int row = mBase + wm + mf * 16 + half * 8 + r_lane;
            if (row < ROWS) {
                if constexpr (STAGE == 1) {
                    __nv_bfloat16* Hh = g_Hh + (size_t)row * OUTD;
                    __nv_bfloat16* Hl = g_Hl + (size_t)row * OUTD;
                    #pragma unroll
                    for (int nf = 0; nf < 8; nf++) {
                        const int col = nBase + wn + nf * 8 + c_lane;
                        float v0 = fmaxf(acc[mf][nf][half * 2]     + __ldg(&bias[col]),     0.f);
                        float v1 = fmaxf(acc[mf][nf][half * 2 + 1] + __ldg(&bias[col + 1]), 0.f);
                        __nv_bfloat16 h0 = __float2bfloat16(v0);
                        __nv_bfloat16 h1 = __float2bfloat16(v1);
                        __nv_bfloat162 hp = {h0, h1};
                        __nv_bfloat162 lp = {__float2bfloat16(v0 - __bfloat162float(h0)),
                                             __float2bfloat16(v1 - __bfloat162float(h1))};
                        *(__nv_bfloat162*)&Hh[col] = hp;
                        *(__nv_bfloat162*)&Hl[col] = lp;
                    }
                } else {
                    const int part = row / NK1;
                    float* Trow = g_T + (size_t)row * OUTD;
                    const float* perow = pe + (size_t)part * OUTD;
                    #pragma unroll
                    for (int nf = 0; nf < 8; nf++) {
                        const int col = nBase + wn + nf * 8 + c_lane;
                        float2 v;
                        v.x = acc[mf][nf][half * 2]     + __ldg(&bias[col])     + __ldg(&perow[col]);
                        v.y = acc[mf][nf][half * 2 + 1] + __ldg(&bias[col + 1]) + __ldg(&perow[col + 1]);
                        *(float2*)&Trow[col] = v;
                    }
                }
            }
        }
    }
}

// ---------------- gather: out[i,:] = g_T[(i&15)*257 + hash[i], :] ----------------
// Streaming stores: the 256MB output is write-once, keep it out of L2 so the
// 16.8MB table stays resident.
__global__ __launch_bounds__(256)
void gather_kernel(const int* __restrict__ hashes, float* __restrict__ out)
{
    const int i = blockIdx.x;                          // b*16 + p
    const int p = i & (P_PARTS - 1);
    const int h = __ldg(&hashes[i]);
    const float4* src = (const float4*)(g_T + (size_t)(p * NK1 + h) * OUTD);
    float4*       dst = (float4*)(out + (size_t)i * OUTD);
    __stwt(&dst[threadIdx.x], src[threadIdx.x]);
}

// ---------------------------------------------------------------------------
extern "C" void kernel_launch(void* const* d_in, const int* in_sizes, int n_in,
                              void* d_out, int out_size)
{
    const int*   hashes = (const int*)  d_in[0];
    const float* emb    = (const float*)d_in[1];
    const float* W1     = (const float*)d_in[2];
    const float* b1     = (const float*)d_in[3];
    const float* W2     = (const float*)d_in[4];
    const float* b2     = (const float*)d_in[5];
    const float* pe     = (const float*)d_in[6];
    float*       out    = (float*)d_out;

    split_emb_kernel<<<512, 256>>>(emb);
    transpose_split_kernel<1><<<dim3(32, 24), dim3(32, 8)>>>(W1, VAE);   // W1 [768][1024]
    transpose_split_kernel<2><<<dim3(32, 32), dim3(32, 8)>>>(W2, OUTD);  // W2 [1024][1024]

    dim3 grid(OUTD / 128, (ROWS + 127) / 128);                           // 8 x 33
    mlp_mma_kernel<1><<<grid, 256>>>(b1, nullptr);
    mlp_mma_kernel<2><<<grid, 256>>>(b2, pe);

    gather_kernel<<<BATCH * P_PARTS, 256>>>(hashes, out);
}

// round 9
// speedup vs baseline: 1.5315x; 1.0119x over previous
#include <cuda_runtime.h>
#include <cuda_bf16.h>
#include <cstdint>

// TokenMapper: out[b,p,:] = (relu(emb[hash[b,p]+p*257] @ W1 + b1) @ W2 + b2) + pe[p]
// Only 16*257=4112 distinct rows -> precompute table T[4112,1024], then gather.
// GEMMs on warp-level mma.sync bf16 (tcgen05 unavailable: toolchain targets
// compute_100, not 100a) with bf16 hi/lo split (3 MMAs) for fp32-grade accuracy.
// R9: 3-stage cp.async pipeline, ONE __syncthreads per k-step (was 2), dynamic smem.

#define P_PARTS 16
#define NK1     257
#define ROWS    (P_PARTS * NK1)     // 4112
#define VAE     768
#define OUTD    1024
#define BATCH   4096

// ---------------- scratch (__device__ globals; alloc-free rule) ----------------
__device__ __align__(16) __nv_bfloat16 g_Ah[ROWS * VAE];    // emb hi
__device__ __align__(16) __nv_bfloat16 g_Al[ROWS * VAE];    // emb lo
__device__ __align__(16) __nv_bfloat16 g_B1h[OUTD * VAE];   // W1^T hi  [n][k]
__device__ __align__(16) __nv_bfloat16 g_B1l[OUTD * VAE];
__device__ __align__(16) __nv_bfloat16 g_B2h[OUTD * OUTD];  // W2^T hi  [n][k]
__device__ __align__(16) __nv_bfloat16 g_B2l[OUTD * OUTD];
__device__ __align__(16) __nv_bfloat16 g_Hh[ROWS * OUTD];   // relu(emb@W1+b1) hi
__device__ __align__(16) __nv_bfloat16 g_Hl[ROWS * OUTD];
__device__ __align__(16) float         g_T [ROWS * OUTD];   // final gather table

// ---------------- PTX helpers (valid at sm_80+, compile on sm_100) ------------
__device__ __forceinline__ uint32_t smem_u32(const void* p) {
    uint32_t a;
    asm("{ .reg .u64 t; cvta.to.shared.u64 t, %1; cvt.u32.u64 %0, t; }" : "=r"(a) : "l"(p));
    return a;
}
__device__ __forceinline__ void cp16(uint32_t dst, const void* src) {
    asm volatile("cp.async.cg.shared.global [%0], [%1], 16;" :: "r"(dst), "l"(src));
}
#define CP_COMMIT() asm volatile("cp.async.commit_group;" ::: "memory")
#define CP_WAIT(n)  asm volatile("cp.async.wait_group %0;" :: "n"(n) : "memory")

__device__ __forceinline__ void ldm_x4(uint32_t* r, uint32_t addr) {
    asm volatile("ldmatrix.sync.aligned.m8n8.x4.shared.b16 {%0,%1,%2,%3}, [%4];"
        : "=r"(r[0]), "=r"(r[1]), "=r"(r[2]), "=r"(r[3]) : "r"(addr));
}
__device__ __forceinline__ void mma_bf16(float* c, const uint32_t* a,
                                         uint32_t b0, uint32_t b1) {
    asm volatile("mma.sync.aligned.m16n8k16.row.col.f32.bf16.bf16.f32 "
        "{%0,%1,%2,%3}, {%4,%5,%6,%7}, {%8,%9}, {%0,%1,%2,%3};"
        : "+f"(c[0]), "+f"(c[1]), "+f"(c[2]), "+f"(c[3])
        : "r"(a[0]), "r"(a[1]), "r"(a[2]), "r"(a[3]), "r"(b0), "r"(b1));
}

// ---------------- prep kernels: bf16 hi/lo splits ----------------
__global__ void split_emb_kernel(const float* __restrict__ src)
{
    const int n = ROWS * VAE;
    for (int i = blockIdx.x * blockDim.x + threadIdx.x; i < n; i += gridDim.x * blockDim.x) {
        float v = src[i];
        __nv_bfloat16 h = __float2bfloat16(v);
        g_Ah[i] = h;
        g_Al[i] = __float2bfloat16(v - __bfloat162float(h));
    }
}

// src [Kdim][1024] -> g_B?h/l [1024][Kdim] (transposed, split)
template<int WHICH>
__global__ void transpose_split_kernel(const float* __restrict__ src, int Kdim)
{
    __nv_bfloat16* dh = (WHICH == 1) ? g_B1h : g_B2h;
    __nv_bfloat16* dl = (WHICH == 1) ? g_B1l : g_B2l;
    __shared__ float t[32][33];
    const int n0 = blockIdx.x * 32, k0 = blockIdx.y * 32;
    const int x = threadIdx.x, y = threadIdx.y;           // block (32, 8)
    #pragma unroll
    for (int i = 0; i < 32; i += 8)
        t[y + i][x] = src[(size_t)(k0 + y + i) * OUTD + n0 + x];
    __syncthreads();
    #pragma unroll
    for (int i = 0; i < 32; i += 8) {
        const int n = n0 + y + i, k = k0 + x;
        float v = t[x][y + i];
        __nv_bfloat16 h = __float2bfloat16(v);
        dh[(size_t)n * Kdim + k] = h;
        dl[(size_t)n * Kdim + k] = __float2bfloat16(v - __bfloat162float(h));
    }
}

// ---------------- mma.sync GEMM: C[128x128 tile] = A @ B^T (split, 3-mma) -----
// STAGE 1: A=(g_Ah,g_Al)[ROWS,768],  B=(g_B1h,l)[1024,768]  -> relu+b1 -> g_Hh/g_Hl
// STAGE 2: A=(g_Hh,g_Hl)[ROWS,1024], B=(g_B2h,l)[1024,1024] -> +b2+pe  -> g_T
#define AP        48                        // smem row pitch bytes (32B data + 16B pad)
#define ARR_BYTES (128 * AP)                // 6144 per array
#define STG_BYTES (4 * ARR_BYTES)           // Ah,Al,Bh,Bl = 24576 per stage
#define N_STAGES  3
#define SMEM_DYN  (N_STAGES * STG_BYTES)    // 73728

template<int STAGE>
__global__ __launch_bounds__(256)
void mlp_mma_kernel(const float* __restrict__ bias, const float* __restrict__ pe)
{
    constexpr int K  = (STAGE == 1) ? VAE : OUTD;
    constexpr int KT = K / 16;

    const __nv_bfloat16* Ah = (STAGE == 1) ? g_Ah  : g_Hh;
    const __nv_bfloat16* Al = (STAGE == 1) ? g_Al  : g_Hl;
    const __nv_bfloat16* Bh = (STAGE == 1) ? g_B1h : g_B2h;
    const __nv_bfloat16* Bl = (STAGE == 1) ? g_B1l : g_B2l;

    extern __shared__ __align__(16) char smem[];

    const uint32_t sb  = smem_u32(smem);
    const int tid   = threadIdx.x;
    const int nBase = blockIdx.x * 128;
    const int mBase = blockIdx.y * 128;
    const int w = tid >> 5, lane = tid & 31;
    const int wm = (w >> 1) * 32;               // 4 warps down (M)
    const int wn = (w & 1) * 64;                // 2 warps across (N)

    float acc[2][8][4];                         // [mf][nf: nt*2+half][4]
    #pragma unroll
    for (int a = 0; a < 2; a++)
        #pragma unroll
        for (int b = 0; b < 8; b++)
            #pragma unroll
            for (int c = 0; c < 4; c++) acc[a][b][c] = 0.f;

    // --- cp.async stage loader: 1024 x 16B per stage (A hi/lo 512, B hi/lo 512)
    auto load_stage = [&](int kt, int s) {
        const uint32_t base = sb + s * STG_BYTES;
        #pragma unroll
        for (int i = tid; i < 1024; i += 256) {
            const int half = i >> 9;            // 0 = A, 1 = B
            const int j    = i & 511;
            const int arr  = j >> 8, rem = j & 255, row = rem >> 1, c = rem & 1;
            const __nv_bfloat16* src;
            if (half == 0) {
                int rg = mBase + row; if (rg >= ROWS) rg = ROWS - 1;
                src = (arr ? Al : Ah) + (size_t)rg * K + kt * 16 + c * 8;
            } else {
                src = (arr ? Bl : Bh) + (size_t)(nBase + row) * K + kt * 16 + c * 8;
            }
            cp16(base + (half * 2 + arr) * ARR_BYTES + row * AP + c * 16, src);
        }
    };

    // prologue: 2 stages in flight
    load_stage(0, 0); CP_COMMIT();
    load_stage(1, 1); CP_COMMIT();

    // ldmatrix x4 lane addressing: mats = [rows 0-7|8-15] x [k-chunk 0|1]
    const int lrow   = (lane & 7) + ((lane >> 3) & 1) * 8;
    const int lchunk = (lane >> 4) * 16;

    for (int kt = 0; kt < KT; kt++) {
        const int s = kt % N_STAGES;
        // retire group kt (keep kt+1 in flight); last iter drains fully
        if (kt + 1 < KT) { CP_WAIT(1); } else { CP_WAIT(0); }
        __syncthreads();    // single barrier per k-step: orders cp completion AND
                            // protects stage (kt+2)%3 (last read at iter kt-1)

        const uint32_t base = sb + s * STG_BYTES;
        uint32_t ah[2][4], al[2][4], bh[4][4], bl[4][4];
        #pragma unroll
        for (int mf = 0; mf < 2; mf++) {
            const uint32_t a = base + (wm + mf * 16 + lrow) * AP + lchunk;
            ldm_x4(ah[mf], a);
            ldm_x4(al[mf], a + ARR_BYTES);
        }
        #pragma unroll
        for (int nt = 0; nt < 4; nt++) {
            const uint32_t b = base + 2 * ARR_BYTES + (wn + nt * 16 + lrow) * AP + lchunk;
            ldm_x4(bh[nt], b);
            ldm_x4(bl[nt], b + ARR_BYTES);
        }

        // refill pipeline: stage kt+2 into buffer (kt+2)%3
        if (kt + 2 < KT) { load_stage(kt + 2, (kt + 2) % N_STAGES); CP_COMMIT(); }

        // Product-grouped ordering: 16 independent MMAs between accumulator reuses.
        #pragma unroll
        for (int mf = 0; mf < 2; mf++)                      // hi * hi
            #pragma unroll
            for (int nt = 0; nt < 4; nt++) {
                mma_bf16(acc[mf][nt * 2],     ah[mf], bh[nt][0], bh[nt][2]);
                mma_bf16(acc[mf][nt * 2 + 1], ah[mf], bh[nt][1], bh[nt][3]);
            }
        #pragma unroll
        for (int mf = 0; mf < 2; mf++)                      // hi * lo
            #pragma unroll
            for (int nt = 0; nt < 4; nt++) {
                mma_bf16(acc[mf][nt * 2],     ah[mf], bl[nt][0], bl[nt][2]);
                mma_bf16(acc[mf][nt * 2 + 1], ah[mf], bl[nt][1], bl[nt][3]);
            }
        #pragma unroll
        for (int mf = 0; mf < 2; mf++)                      // lo * hi
            #pragma unroll
            for (int nt = 0; nt < 4; nt++) {
                mma_bf16(acc[mf][nt * 2],     al[mf], bh[nt][0], bh[nt][2]);
                mma_bf16(acc[mf][nt * 2 + 1], al[mf], bh[nt][1], bh[nt][3]);
            }
    }

    // --- epilogue: direct stores from accumulators (no smem staging) ---------
    const int r_lane = lane >> 2;               // 0..7
    const int c_lane = (lane & 3) * 2;          // 0,2,4,6
    #pragma unroll
    for (int mf = 0; mf < 2; mf++) {
        #pragma unroll
        for (int half = 0; half < 2; half++) {
            const int row = mBase + wm + mf * 16 + half * 8 + r_lane;
            if (row < ROWS) {
                if constexpr (STAGE == 1) {
                    __nv_bfloat16* Hh = g_Hh + (size_t)row * OUTD;
                    __nv_bfloat16* Hl = g_Hl + (size_t)row * OUTD;
                    #pragma unroll
                    for (int nf = 0; nf < 8; nf++) {
                        const int col = nBase + wn + nf * 8 + c_lane;
                        float v0 = fmaxf(acc[mf][nf][half * 2]     + __ldg(&bias[col]),     0.f);
                        float v1 = fmaxf(acc[mf][nf][half * 2 + 1] + __ldg(&bias[col + 1]), 0.f);
                        __nv_bfloat16 h0 = __float2bfloat16(v0);
                        __nv_bfloat16 h1 = __float2bfloat16(v1);
                        __nv_bfloat162 hp = {h0, h1};
                        __nv_bfloat162 lp = {__float2bfloat16(v0 - __bfloat162float(h0)),
                                             __float2bfloat16(v1 - __bfloat162float(h1))};
                        *(__nv_bfloat162*)&Hh[col] = hp;
                        *(__nv_bfloat162*)&Hl[col] = lp;
                    }
                } else {
                    const int part = row / NK1;
                    float* Trow = g_T + (size_t)row * OUTD;
                    const float* perow = pe + (size_t)part * OUTD;
                    #pragma unroll
                    for (int nf = 0; nf < 8; nf++) {
                        const int col = nBase + wn + nf * 8 + c_lane;
                        float2 v;
                        v.x = acc[mf][nf][half * 2]     + __ldg(&bias[col])     + __ldg(&perow[col]);
                        v.y = acc[mf][nf][half * 2 + 1] + __ldg(&bias[col + 1]) + __ldg(&perow[col + 1]);
                        *(float2*)&Trow[col] = v;
                    }
                }
            }
        }
    }
}

// ---------------- gather: out[i,:] = g_T[(i&15)*257 + hash[i], :] ----------------
// Streaming stores: the 256MB output is write-once, keep it out of L2 so the
// 16.8MB table stays resident.
__global__ __launch_bounds__(256)
void gather_kernel(const int* __restrict__ hashes, float* __restrict__ out)
{
    const int i = blockIdx.x;                          // b*16 + p
    const int p = i & (P_PARTS - 1);
    const int h = __ldg(&hashes[i]);
    const float4* src = (const float4*)(g_T + (size_t)(p * NK1 + h) * OUTD);
    float4*       dst = (float4*)(out + (size_t)i * OUTD);
    __stwt(&dst[threadIdx.x], src[threadIdx.x]);
}

// ---------------------------------------------------------------------------
extern "C" void kernel_launch(void* const* d_in, const int* in_sizes, int n_in,
                              void* d_out, int out_size)
{
    const int*   hashes = (const int*)  d_in[0];
    const float* emb    = (const float*)d_in[1];
    const float* W1     = (const float*)d_in[2];
    const float* b1     = (const float*)d_in[3];
    const float* W2     = (const float*)d_in[4];
    const float* b2     = (const float*)d_in[5];
    const float* pe     = (const float*)d_in[6];
    float*       out    = (float*)d_out;

    // Host-side attribute config (no allocation, capture-legal, idempotent).
    cudaFuncSetAttribute(mlp_mma_kernel<1>, cudaFuncAttributeMaxDynamicSharedMemorySize, SMEM_DYN);
    cudaFuncSetAttribute(mlp_mma_kernel<2>, cudaFuncAttributeMaxDynamicSharedMemorySize, SMEM_DYN);

    split_emb_kernel<<<512, 256>>>(emb);
    transpose_split_kernel<1><<<dim3(32, 24), dim3(32, 8)>>>(W1, VAE);   // W1 [768][1024]
    transpose_split_kernel<2><<<dim3(32, 32), dim3(32, 8)>>>(W2, OUTD);  // W2 [1024][1024]

    dim3 grid(OUTD / 128, (ROWS + 127) / 128);                           // 8 x 33
    mlp_mma_kernel<1><<<grid, 256, SMEM_DYN>>>(b1, nullptr);
    mlp_mma_kernel<2><<<grid, 256, SMEM_DYN>>>(b2, pe);

    gather_kernel<<<BATCH * P_PARTS, 256>>>(hashes, out);
}

// round 10
// speedup vs baseline: 1.7004x; 1.1103x over previous
#include <cuda_runtime.h>
#include <cuda_bf16.h>
#include <cstdint>

// TokenMapper: out[b,p,:] = (relu(emb[hash[b,p]+p*257] @ W1 + b1) @ W2 + b2) + pe[p]
// Only 16*257=4112 distinct rows -> precompute table T[4112,1024], then gather.
// GEMMs on warp-level mma.sync bf16 with bf16 hi/lo split (3 MMAs).
// R10: fragment double-buffering — ldmatrix for k-step h+1 issued right after
// the barrier, before h's MMAs, so LDSM latency hides under tensor work.

#define P_PARTS 16
#define NK1     257
#define ROWS    (P_PARTS * NK1)     // 4112
#define VAE     768
#define OUTD    1024
#define BATCH   4096

// ---------------- scratch (__device__ globals; alloc-free rule) ----------------
__device__ __align__(16) __nv_bfloat16 g_Ah[ROWS * VAE];    // emb hi
__device__ __align__(16) __nv_bfloat16 g_Al[ROWS * VAE];    // emb lo
__device__ __align__(16) __nv_bfloat16 g_B1h[OUTD * VAE];   // W1^T hi  [n][k]
__device__ __align__(16) __nv_bfloat16 g_B1l[OUTD * VAE];
__device__ __align__(16) __nv_bfloat16 g_B2h[OUTD * OUTD];  // W2^T hi  [n][k]
__device__ __align__(16) __nv_bfloat16 g_B2l[OUTD * OUTD];
__device__ __align__(16) __nv_bfloat16 g_Hh[ROWS * OUTD];   // relu(emb@W1+b1) hi
__device__ __align__(16) __nv_bfloat16 g_Hl[ROWS * OUTD];
__device__ __align__(16) float         g_T [ROWS * OUTD];   // final gather table

// ---------------- PTX helpers (valid at sm_80+, compile on sm_100) ------------
__device__ __forceinline__ uint32_t smem_u32(const void* p) {
    uint32_t a;
    asm("{ .reg .u64 t; cvta.to.shared.u64 t, %1; cvt.u32.u64 %0, t; }" : "=r"(a) : "l"(p));
    return a;
}
__device__ __forceinline__ void cp16(uint32_t dst, const void* src) {
    asm volatile("cp.async.cg.shared.global [%0], [%1], 16;" :: "r"(dst), "l"(src));
}
#define CP_COMMIT() asm volatile("cp.async.commit_group;" ::: "memory")
#define CP_WAIT(n)  asm volatile("cp.async.wait_group %0;" :: "n"(n) : "memory")

__device__ __forceinline__ void ldm_x4(uint32_t* r, uint32_t addr) {
    asm volatile("ldmatrix.sync.aligned.m8n8.x4.shared.b16 {%0,%1,%2,%3}, [%4];"
        : "=r"(r[0]), "=r"(r[1]), "=r"(r[2]), "=r"(r[3]) : "r"(addr));
}
__device__ __forceinline__ void mma_bf16(float* c, const uint32_t* a,
                                         uint32_t b0, uint32_t b1) {
    asm volatile("mma.sync.aligned.m16n8k16.row.col.f32.bf16.bf16.f32 "
        "{%0,%1,%2,%3}, {%4,%5,%6,%7}, {%8,%9}, {%0,%1,%2,%3};"
        : "+f"(c[0]), "+f"(c[1]), "+f"(c[2]), "+f"(c[3])
        : "r"(a[0]), "r"(a[1]), "r"(a[2]), "r"(a[3]), "r"(b0), "r"(b1));
}

// ---------------- prep kernels: bf16 hi/lo splits ----------------
__global__ void split_emb_kernel(const float* __restrict__ src)
{
    const int n = ROWS * VAE;
    for (int i = blockIdx.x * blockDim.x + threadIdx.x; i < n; i += gridDim.x * blockDim.x) {
        float v = src[i];
        __nv_bfloat16 h = __float2bfloat16(v);
        g_Ah[i] = h;
        g_Al[i] = __float2bfloat16(v - __bfloat162float(h));
    }
}

// src [Kdim][1024] -> g_B?h/l [1024][Kdim] (transposed, split)
template<int WHICH>
__global__ void transpose_split_kernel(const float* __restrict__ src, int Kdim)
{
    __nv_bfloat16* dh = (WHICH == 1) ? g_B1h : g_B2h;
    __nv_bfloat16* dl = (WHICH == 1) ? g_B1l : g_B2l;
    __shared__ float t[32][33];
    const int n0 = blockIdx.x * 32, k0 = blockIdx.y * 32;
    const int x = threadIdx.x, y = threadIdx.y;           // block (32, 8)
    #pragma unroll
    for (int i = 0; i < 32; i += 8)
        t[y + i][x] = src[(size_t)(k0 + y + i) * OUTD + n0 + x];
    __syncthreads();
    #pragma unroll
    for (int i = 0; i < 32; i += 8) {
        const int n = n0 + y + i, k = k0 + x;
        float v = t[x][y + i];
        __nv_bfloat16 h = __float2bfloat16(v);
        dh[(size_t)n * Kdim + k] = h;
        dl[(size_t)n * Kdim + k] = __float2bfloat16(v - __bfloat162float(h));
    }
}

// ---------------- mma.sync GEMM: C[128x128 tile] = A @ B^T (split, 3-mma) -----
#define AP        48                        // smem row pitch bytes (32B data + 16B pad)
#define ARR_BYTES (128 * AP)                // 6144 per array
#define STG_BYTES (4 * ARR_BYTES)           // Ah,Al,Bh,Bl = 24576 per stage
#define N_STAGES  3
#define SMEM_DYN  (N_STAGES * STG_BYTES)    // 73728

struct Frags {
    uint32_t ah[2][4], al[2][4], bh[4][4], bl[4][4];
};

__device__ __forceinline__ void load_frags(Frags& F, uint32_t base,
                                           int wm, int wn, int lrow, int lchunk)
{
    #pragma unroll
    for (int mf = 0; mf < 2; mf++) {
        const uint32_t a = base + (wm + mf * 16 + lrow) * AP + lchunk;
        ldm_x4(F.ah[mf], a);
        ldm_x4(F.al[mf], a + ARR_BYTES);
    }
    #pragma unroll
    for (int nt = 0; nt < 4; nt++) {
        const uint32_t b = base + 2 * ARR_BYTES + (wn + nt * 16 + lrow) * AP + lchunk;
        ldm_x4(F.bh[nt], b);
        ldm_x4(F.bl[nt], b + ARR_BYTES);
    }
}

__device__ __forceinline__ void mma_all(float acc[2][8][4], const Frags& F)
{
    // Product-grouped ordering: 16 independent MMAs between accumulator reuses.
    #pragma unroll
    for (int mf = 0; mf < 2; mf++)                      // hi * hi
        #pragma unroll
        for (int nt = 0; nt < 4; nt++) {
            mma_bf16(acc[mf][nt * 2],     F.ah[mf], F.bh[nt][0], F.bh[nt][2]);
            mma_bf16(acc[mf][nt * 2 + 1], F.ah[mf], F.bh[nt][1], F.bh[nt][3]);
        }
    #pragma unroll
    for (int mf = 0; mf < 2; mf++)                      // hi * lo
        #pragma unroll
        for (int nt = 0; nt < 4; nt++) {
            mma_bf16(acc[mf][nt * 2],     F.ah[mf], F.bl[nt][0], F.bl[nt][2]);
            mma_bf16(acc[mf][nt * 2 + 1], F.ah[mf], F.bl[nt][1], F.bl[nt][3]);
        }
    #pragma unroll
    for (int mf = 0; mf < 2; mf++)                      // lo * hi
        #pragma unroll
        for (int nt = 0; nt < 4; nt++) {
            mma_bf16(acc[mf][nt * 2],     F.al[mf], F.bh[nt][0], F.bh[nt][2]);
            mma_bf16(acc[mf][nt * 2 + 1], F.al[mf], F.bh[nt][1], F.bh[nt][3]);
        }
}

// STAGE 1: A=(g_Ah,g_Al)[ROWS,768],  B=(g_B1h,l)[1024,768]  -> relu+b1 -> g_Hh/g_Hl
// STAGE 2: A=(g_Hh,g_Hl)[ROWS,1024], B=(g_B2h,l)[1024,1024] -> +b2+pe  -> g_T
template<int STAGE>
__global__ __launch_bounds__(256)
void mlp_mma_kernel(const float* __restrict__ bias, const float* __restrict__ pe)
{
    constexpr int K  = (STAGE == 1) ? VAE : OUTD;
    constexpr int KT = K / 16;                  // 48 / 64, both even

    const __nv_bfloat16* Ah = (STAGE == 1) ? g_Ah  : g_Hh;
    const __nv_bfloat16* Al = (STAGE == 1) ? g_Al  : g_Hl;
    const __nv_bfloat16* Bh = (STAGE == 1) ? g_B1h : g_B2h;
    const __nv_bfloat16* Bl = (STAGE == 1) ? g_B1l : g_B2l;

    extern __shared__ __align__(16) char smem[];

    const uint32_t sb  = smem_u32(smem);
    const int tid   = threadIdx.x;
    const int nBase = blockIdx.x * 128;
    const int mBase = blockIdx.y * 128;
    const int w = tid >> 5, lane = tid & 31;
    const int wm = (w >> 1) * 32;               // 4 warps down (M)
    const int wn = (w & 1) * 64;                // 2 warps across (N)

    float acc[2][8][4];
    #pragma unroll
    for (int a = 0; a < 2; a++)
        #pragma unroll
        for (int b = 0; b < 8; b++)
            #pragma unroll
            for (int c = 0; c < 4; c++) acc[a][b][c] = 0.f;

    // --- cp.async stage loader (by smem base): 1024 x 16B per stage ----------
    auto load_stage = [&](int kt, uint32_t base) {
        #pragma unroll
        for (int i = tid; i < 1024; i += 256) {
            const int half = i >> 9;            // 0 = A, 1 = B
            const int j    = i & 511;
            const int arr  = j >> 8, rem = j & 255, row = rem >> 1, c = rem & 1;
            const __nv_bfloat16* src;
            if (half == 0) {
                int rg = mBase + row; if (rg >= ROWS) rg = ROWS - 1;
                src = (arr ? Al : Ah) + (size_t)rg * K + kt * 16 + c * 8;
            } else {
                src = (arr ? Bl : Bh) + (size_t)(nBase + row) * K + kt * 16 + c * 8;
            }
            cp16(base + (half * 2 + arr) * ARR_BYTES + row * AP + c * 16, src);
        }
    };

    // ldmatrix x4 lane addressing
    const int lrow   = (lane & 7) + ((lane >> 3) & 1) * 8;
    const int lchunk = (lane >> 4) * 16;

    // rotating stage bases: c = stage h, n = h+1, p = h+2
    uint32_t csm = sb, nsm = sb + STG_BYTES, psm = sb + 2 * STG_BYTES;

    // prologue: fill all 3 stages; frags for stage 0 into F0
    load_stage(0, csm); CP_COMMIT();
    load_stage(1, nsm); CP_COMMIT();
    load_stage(2, psm); CP_COMMIT();
    CP_WAIT(2);
    __syncthreads();
    Frags F0, F1;
    load_frags(F0, csm, wm, wn, lrow, lchunk);

    #define MAIN_STEP(h, CUR, NXT)                                              \
    {                                                                           \
        if ((h) + 2 < KT) { CP_WAIT(1); } else { CP_WAIT(0); }                  \
        __syncthreads();  /* stage h+1 visible; buffer csm (stage h) now dead   \
                             for smem (frags in regs) and safe to overwrite */  \
        if ((h) + 1 < KT) load_frags(NXT, nsm, wm, wn, lrow, lchunk);           \
        if ((h) + 3 < KT) { load_stage((h) + 3, csm); CP_COMMIT(); }            \
        mma_all(acc, CUR);                                                      \
        uint32_t t_ = csm; csm = nsm; nsm = psm; psm = t_;                      \
    }

    for (int h = 0; h < KT; h += 2) {
        MAIN_STEP(h,     F0, F1);
        MAIN_STEP(h + 1, F1, F0);
    }
    #undef MAIN_STEP

    // --- epilogue: direct stores from accumulators ---------------------------
    const int r_lane = lane >> 2;               // 0..7
    const int c_lane = (lane & 3) * 2;          // 0,2,4,6
    #pragma unroll
    for (int mf = 0; mf < 2; mf++) {
        #pragma unroll
        for (int half = 0; half < 2; half++) {
            const int row = mBase + wm + mf * 16 + half * 8 + r_lane;
            if (row < ROWS) {
                if constexpr (STAGE == 1) {
                    __nv_bfloat16* Hh = g_Hh + (size_t)row * OUTD;
                    __nv_bfloat16* Hl = g_Hl + (size_t)row * OUTD;
                    #pragma unroll
                    for (int nf = 0; nf < 8; nf++) {
                        const int col = nBase + wn + nf * 8 + c_lane;
                        float v0 = fmaxf(acc[mf][nf][half * 2]     + __ldg(&bias[col]),     0.f);
                        float v1 = fmaxf(acc[mf][nf][half * 2 + 1] + __ldg(&bias[col + 1]), 0.f);
                        __nv_bfloat16 h0 = __float2bfloat16(v0);
                        __nv_bfloat16 h1 = __float2bfloat16(v1);
                        __nv_bfloat162 hp = {h0, h1};
                        __nv_bfloat162 lp = {__float2bfloat16(v0 - __bfloat162float(h0)),
                                             __float2bfloat16(v1 - __bfloat162float(h1))};
                        *(__nv_bfloat162*)&Hh[col] = hp;
                        *(__nv_bfloat162*)&Hl[col] = lp;
                    }
                } else {
                    const int part = row / NK1;
                    float* Trow = g_T + (size_t)row * OUTD;
                    const float* perow = pe + (size_t)part * OUTD;
                    #pragma unroll
                    for (int nf = 0; nf < 8; nf++) {
                        const int col = nBase + wn + nf * 8 + c_lane;
                        float2 v;
                        v.x = acc[mf][nf][half * 2]     + __ldg(&bias[col])     + __ldg(&perow[col]);
                        v.y = acc[mf][nf][half * 2 + 1] + __ldg(&bias[col + 1]) + __ldg(&perow[col + 1]);
                        *(float2*)&Trow[col] = v;
                    }
                }
            }
        }
    }
}

// ---------------- gather: out[i,:] = g_T[(i&15)*257 + hash[i], :] ----------------
__global__ __launch_bounds__(256)
void gather_kernel(const int* __restrict__ hashes, float* __restrict__ out)
{
    const int i = blockIdx.x;                          // b*16 + p
    const int p = i & (P_PARTS - 1);
    const int h = __ldg(&hashes[i]);
    const float4* src = (const float4*)(g_T + (size_t)(p * NK1 + h) * OUTD);
    float4*       dst = (float4*)(out + (size_t)i * OUTD);
    __stwt(&dst[threadIdx.x], src[threadIdx.x]);
}

// ---------------------------------------------------------------------------
extern "C" void kernel_launch(void* const* d_in, const int* in_sizes, int n_in,
                              void* d_out, int out_size)
{
    const int*   hashes = (const int*)  d_in[0];
    const float* emb    = (const float*)d_in[1];
    const float* W1     = (const float*)d_in[2];
    const float* b1     = (const float*)d_in[3];
    const float* W2     = (const float*)d_in[4];
    const float* b2     = (const float*)d_in[5];
    const float* pe     = (const float*)d_in[6];
    float*       out    = (float*)d_out;

    cudaFuncSetAttribute(mlp_mma_kernel<1>, cudaFuncAttributeMaxDynamicSharedMemorySize, SMEM_DYN);
    cudaFuncSetAttribute(mlp_mma_kernel<2>, cudaFuncAttributeMaxDynamicSharedMemorySize, SMEM_DYN);

    split_emb_kernel<<<512, 256>>>(emb);
    transpose_split_kernel<1><<<dim3(32, 24), dim3(32, 8)>>>(W1, VAE);   // W1 [768][1024]
    transpose_split_kernel<2><<<dim3(32, 32), dim3(32, 8)>>>(W2, OUTD);  // W2 [1024][1024]

    dim3 grid(OUTD / 128, (ROWS + 127) / 128);                           // 8 x 33
    mlp_mma_kernel<1><<<grid, 256, SMEM_DYN>>>(b1, nullptr);
    mlp_mma_kernel<2><<<grid, 256, SMEM_DYN>>>(b2, pe);

    gather_kernel<<<BATCH * P_PARTS, 256>>>(hashes, out);
}